// round 15
// baseline (speedup 1.0000x reference)
#include <cuda_runtime.h>
#include <cstdint>

// Per-row exact top-k masking (keep k largest/smallest along last axis, zero rest).
// One warp per row of C=768 floats. Level-1: SWAR byte-plane binary search over
// all 768 top-bytes. The m active candidates (typically 15-55) are compacted to
// <=2 per lane via a tiny smem strip; remaining 3 bytes resolved by ballot-count
// binary search (single-ballot fast path when m<=32) with early unique-survivor
// exit. m>64 falls back to exact masked plane searches; m==1 extracts directly.
// R15: 64-thread CTAs (2 warps) -> 21 CTAs/SM at 48 regs = 42 warps/SM (vs 40
// with 128-thread CTAs), exploiting RF packing; launch_bounds(64,21) caps at
// exactly 48 regs so the instruction stream is unchanged from the R12 optimum.

#define FULL_MASK 0xFFFFFFFFu

constexpr int C_DIM = 768;
constexpr int V4    = 6;     // float4 loads per lane (24 values/lane)
constexpr int WARPS = 2;     // rows per block (64-thread CTAs)

__device__ __forceinline__ unsigned f2ord(unsigned b) {
    return b ^ (unsigned)(((int)b >> 31) | 0x80000000);
}
__device__ __forceinline__ unsigned ord2f(unsigned u) {
    return u ^ (unsigned)(0x80000000u | ~((unsigned)((int)u >> 31)));
}

// Level-1 (mask-free) byte search: all 768 bytes active.
__device__ __forceinline__ int search_plane_l1(const unsigned* pl, const unsigned* plm,
                                               int& r, int& m)
{
    const unsigned REP1 = 0x01010101u;
    const unsigned H    = 0x80808080u;
    unsigned acc = 0;
    #pragma unroll
    for (int j = 0; j < V4; j++) acc = __dp4a(pl[j] & H, REP1, acc);
    const int n1 = (int)(__reduce_add_sync(FULL_MASK, acc) >> 7);

    int lo = 0, hi = 128, flo, fhi, base;
    if (n1 >= r) {   // threshold byte has bit7 set
        base = 128; flo = n1; fhi = 0;
        #pragma unroll 1
        for (int it = 0; it < 7; it++) {
            int mid = (lo + hi) >> 1;
            unsigned crep = (unsigned)(128 - mid) * REP1;
            unsigned a2 = 0;
            #pragma unroll
            for (int j = 0; j < V4; j++) {
                unsigned s = plm[j] + crep;           // bit7 <=> low7 >= mid
                a2 = __dp4a(s & pl[j] & H, REP1, a2);
            }
            int cnt = (int)(__reduce_add_sync(FULL_MASK, a2) >> 7);
            if (cnt >= r) { lo = mid; flo = cnt; } else { hi = mid; fhi = cnt; }
        }
    } else {         // threshold byte has bit7 clear
        base = 0; flo = m; fhi = n1;
        #pragma unroll 1
        for (int it = 0; it < 7; it++) {
            int mid = (lo + hi) >> 1;
            unsigned crep = (unsigned)(128 - mid) * REP1;
            unsigned a2 = 0;
            #pragma unroll
            for (int j = 0; j < V4; j++) {
                unsigned s = plm[j] + crep;
                a2 = __dp4a((s | pl[j]) & H, REP1, a2);
            }
            int cnt = (int)(__reduce_add_sync(FULL_MASK, a2) >> 7);
            if (cnt >= r) { lo = mid; flo = cnt; } else { hi = mid; fhi = cnt; }
        }
    }
    r -= fhi;
    m  = flo - fhi;
    return base + lo;
}

// Masked byte search (fallback levels). msk: 0x80 per active byte.
__device__ __forceinline__ int search_plane(const unsigned* pl, const unsigned* plm,
                                            const unsigned* msk, int& r, int& m)
{
    const unsigned REP1 = 0x01010101u;
    unsigned acc = 0;
    #pragma unroll
    for (int j = 0; j < V4; j++) acc = __dp4a(pl[j] & msk[j], REP1, acc);
    const int n1 = (int)(__reduce_add_sync(FULL_MASK, acc) >> 7);

    int lo = 0, hi = 128, flo, fhi, base;
    if (n1 >= r) {
        base = 128; flo = n1; fhi = 0;
        #pragma unroll 1
        for (int it = 0; it < 7; it++) {
            int mid = (lo + hi) >> 1;
            unsigned crep = (unsigned)(128 - mid) * REP1;
            unsigned a2 = 0;
            #pragma unroll
            for (int j = 0; j < V4; j++) {
                unsigned s = plm[j] + crep;
                a2 = __dp4a(s & pl[j] & msk[j], REP1, a2);
            }
            int cnt = (int)(__reduce_add_sync(FULL_MASK, a2) >> 7);
            if (cnt >= r) { lo = mid; flo = cnt; } else { hi = mid; fhi = cnt; }
        }
    } else {
        base = 0; flo = m; fhi = n1;
        #pragma unroll 1
        for (int it = 0; it < 7; it++) {
            int mid = (lo + hi) >> 1;
            unsigned crep = (unsigned)(128 - mid) * REP1;
            unsigned a2 = 0;
            #pragma unroll
            for (int j = 0; j < V4; j++) {
                unsigned s = plm[j] + crep;
                a2 = __dp4a((s | pl[j]) & msk[j], REP1, a2);
            }
            int cnt = (int)(__reduce_add_sync(FULL_MASK, a2) >> 7);
            if (cnt >= r) { lo = mid; flo = cnt; } else { hi = mid; fhi = cnt; }
        }
    }
    r -= fhi;
    m  = flo - fhi;
    return base + lo;
}

// First refine: msk is BORN here as the byte-equality mask.
__device__ __forceinline__ void refine_mask_init(unsigned* msk, const unsigned* pl,
                                                 const unsigned* plm, int d)
{
    const unsigned NH = 0x7F7F7F7Fu;
    const unsigned H  = 0x80808080u;
    const unsigned drep = (unsigned)d * 0x01010101u;
    const unsigned dr7  = drep & NH;
    #pragma unroll
    for (int j = 0; j < V4; j++) {
        unsigned z = pl[j] ^ drep;
        unsigned a = (plm[j] ^ dr7) + NH;
        msk[j] = ~a & ~z & H;                    // one LOP3
    }
}

// Subsequent refines: intersect with existing msk.
__device__ __forceinline__ void refine_mask(unsigned* msk, const unsigned* pl,
                                            const unsigned* plm, int d)
{
    const unsigned NH = 0x7F7F7F7Fu;
    const unsigned drep = (unsigned)d * 0x01010101u;
    const unsigned dr7  = drep & NH;
    #pragma unroll
    for (int j = 0; j < V4; j++) {
        unsigned z = pl[j] ^ drep;
        unsigned a = (plm[j] ^ dr7) + NH;
        msk[j] = ~a & ~z & msk[j];               // one LOP3 (msk is 0x80-only)
    }
}

// Exactly one active byte remains: return its full ordered value (warp-wide).
__device__ __forceinline__ unsigned extract_unique(const unsigned* msk,
                                                   const float* f, unsigned flip)
{
    unsigned best = 0;
    #pragma unroll
    for (int j = 0; j < V4; j++) {
        unsigned y = msk[j];
        if (y) {
            #pragma unroll
            for (int b = 0; b < 4; b++)
                if (y & (0x80u << (8*b)))
                    best = f2ord(__float_as_uint(f[4*j+b])) ^ flip;
        }
    }
    return __reduce_max_sync(FULL_MASK, best);
}

__global__ __launch_bounds__(WARPS * 32, 21)
void topk_mask_kernel(const float* __restrict__ x,
                      const int* __restrict__ kptr,
                      const int* __restrict__ lptr,
                      float* __restrict__ out,
                      int nrows)
{
    __shared__ unsigned s_cand[WARPS][64];   // 0.5 KB: compacted candidates

    const int warp = threadIdx.x >> 5;
    const int lane = threadIdx.x & 31;
    const int row  = blockIdx.x * WARPS + warp;
    if (row >= nrows) return;

    const int k       = *kptr;
    const int largest = *lptr;
    const unsigned flip = largest ? 0u : 0xFFFFFFFFu;

    const float4* __restrict__ xin =
        reinterpret_cast<const float4*>(x + (size_t)row * C_DIM);
    float4* __restrict__ xout =
        reinterpret_cast<float4*>(out + (size_t)row * C_DIM);

    const unsigned H  = 0x80808080u;
    const unsigned NH = 0x7F7F7F7Fu;
    const unsigned HX = H ^ flip;

    // ---- load x (streaming); pack ordered top-byte plane into p/pm ----
    float f[V4 * 4];
    unsigned p[V4], pm[V4], msk[V4];
    #pragma unroll
    for (int j = 0; j < V4; j++) {
        float4 v = __ldcs(&xin[lane + 32 * j]);
        f[4*j+0] = v.x; f[4*j+1] = v.y; f[4*j+2] = v.z; f[4*j+3] = v.w;
        unsigned p01 = __byte_perm(__float_as_uint(v.x), __float_as_uint(v.y), 0x0073);
        unsigned p23 = __byte_perm(__float_as_uint(v.z), __float_as_uint(v.w), 0x0073);
        unsigned pk  = __byte_perm(p01, p23, 0x5410);
        unsigned s   = pk & H;
        unsigned mm  = (s >> 7) * 0x7Fu;   // ordered-byte transform for negatives
        p[j]  = pk ^ mm ^ HX;
        pm[j] = p[j] & NH;
    }

    // ---- level 1: top byte (mask-free) ----
    int r = k, m = C_DIM;
    int d = search_plane_l1(p, pm, r, m);
    unsigned cur = (unsigned)d << 24;
    refine_mask_init(msk, p, pm, d);

    unsigned thr_ord;

    if (m == 1) {
        thr_ord = extract_unique(msk, f, flip);
    } else if (m <= 64) {
        // ---- compact the m candidates into smem (scan + predicated writes) ----
        int ci = 0;
        #pragma unroll
        for (int j = 0; j < V4; j++) ci += __popc(msk[j]);
        int sc = ci;
        #pragma unroll
        for (int sh = 1; sh < 32; sh <<= 1) {
            int t = __shfl_up_sync(FULL_MASK, sc, sh);
            if (lane >= sh) sc += t;
        }
        unsigned* cand = s_cand[warp];
        int pos = sc - ci;                       // exclusive prefix
        #pragma unroll
        for (int j = 0; j < V4; j++) {
            unsigned y = msk[j];
            if (y) {
                #pragma unroll
                for (int b = 0; b < 4; b++)
                    if (y & (0x80u << (8*b)))
                        cand[pos++] = f2ord(__float_as_uint(f[4*j+b])) ^ flip;
            }
        }
        __syncwarp();

        if (m <= 32) {
            // single candidate per lane: one ballot per probe
            bool a0 = lane < m;
            unsigned c0 = a0 ? cand[lane] : 0u;
            bool res2 = false;
            #pragma unroll 1
            for (int sh = 16; sh >= 0; sh -= 8) {
                int b0v = (int)((c0 >> sh) & 0xFFu);
                int lo = 0, hi = 256, fhi = 0;
                #pragma unroll 1
                for (int it = 0; it < 8; it++) {
                    int mid = (lo + hi) >> 1;
                    int cnt = __popc(__ballot_sync(FULL_MASK, a0 && (b0v >= mid)));
                    if (cnt >= r) { lo = mid; } else { hi = mid; fhi = cnt; }
                }
                r -= fhi;
                cur |= (unsigned)lo << sh;
                a0 = a0 && (b0v == lo);
                if (__popc(__ballot_sync(FULL_MASK, a0)) == 1) {
                    unsigned best = a0 ? c0 : 0u;
                    thr_ord = __reduce_max_sync(FULL_MASK, best);
                    res2 = true;
                    break;
                }
            }
            if (!res2) thr_ord = cur;
        } else {
            // <=2 candidates per lane
            bool a0 = true;                      // lane < m (m > 32)
            bool a1 = 32 + lane < m;
            unsigned c0 = cand[lane];
            unsigned c1 = a1 ? cand[32 + lane] : 0u;
            bool res2 = false;
            #pragma unroll 1
            for (int sh = 16; sh >= 0; sh -= 8) {
                int b0v = (int)((c0 >> sh) & 0xFFu);
                int b1v = (int)((c1 >> sh) & 0xFFu);
                int lo = 0, hi = 256, fhi = 0;
                #pragma unroll 1
                for (int it = 0; it < 8; it++) {
                    int mid = (lo + hi) >> 1;
                    unsigned bal0 = __ballot_sync(FULL_MASK, a0 && (b0v >= mid));
                    unsigned bal1 = __ballot_sync(FULL_MASK, a1 && (b1v >= mid));
                    int cnt = __popc(bal0) + __popc(bal1);
                    if (cnt >= r) { lo = mid; } else { hi = mid; fhi = cnt; }
                }
                r -= fhi;
                cur |= (unsigned)lo << sh;
                a0 = a0 && (b0v == lo);
                a1 = a1 && (b1v == lo);
                unsigned s0 = __ballot_sync(FULL_MASK, a0);
                unsigned s1 = __ballot_sync(FULL_MASK, a1);
                if (__popc(s0) + __popc(s1) == 1) {
                    unsigned best = a0 ? c0 : (a1 ? c1 : 0u);
                    thr_ord = __reduce_max_sync(FULL_MASK, best);
                    res2 = true;
                    break;
                }
            }
            if (!res2) thr_ord = cur;
        }
    } else {
        // ---- rare heavy bin (m > 64): exact masked plane searches over
        //      ordered-converted data, bytes 2,1,0. ----
        #pragma unroll
        for (int i = 0; i < V4 * 4; i++)
            f[i] = __uint_as_float(f2ord(__float_as_uint(f[i])) ^ flip);

        #pragma unroll
        for (int j = 0; j < V4; j++) {
            unsigned a01 = __byte_perm(__float_as_uint(f[4*j+0]),
                                       __float_as_uint(f[4*j+1]), 0x0062);
            unsigned a23 = __byte_perm(__float_as_uint(f[4*j+2]),
                                       __float_as_uint(f[4*j+3]), 0x0062);
            p[j]  = __byte_perm(a01, a23, 0x5410);   // byte2 plane (ordered)
            pm[j] = p[j] & NH;
        }
        int d2 = search_plane(p, pm, msk, r, m);
        cur |= (unsigned)d2 << 16;
        refine_mask(msk, p, pm, d2);

        #pragma unroll
        for (int j = 0; j < V4; j++) {
            unsigned a01 = __byte_perm(__float_as_uint(f[4*j+0]),
                                       __float_as_uint(f[4*j+1]), 0x0051);
            unsigned a23 = __byte_perm(__float_as_uint(f[4*j+2]),
                                       __float_as_uint(f[4*j+3]), 0x0051);
            p[j]  = __byte_perm(a01, a23, 0x5410);   // byte1 plane (ordered)
            pm[j] = p[j] & NH;
        }
        int d3 = search_plane(p, pm, msk, r, m);
        cur |= (unsigned)d3 << 8;
        refine_mask(msk, p, pm, d3);

        #pragma unroll
        for (int j = 0; j < V4; j++) {
            unsigned a01 = __byte_perm(__float_as_uint(f[4*j+0]),
                                       __float_as_uint(f[4*j+1]), 0x0040);
            unsigned a23 = __byte_perm(__float_as_uint(f[4*j+2]),
                                       __float_as_uint(f[4*j+3]), 0x0040);
            p[j]  = __byte_perm(a01, a23, 0x5410);   // byte0 plane (ordered)
            pm[j] = p[j] & NH;
        }
        int d4 = search_plane(p, pm, msk, r, m);
        cur |= (unsigned)d4;
        thr_ord = cur;                               // exact (duplicates too)

        // restore f to raw floats
        #pragma unroll
        for (int i = 0; i < V4 * 4; i++)
            f[i] = __uint_as_float(ord2f(__float_as_uint(f[i]) ^ flip));
    }

    // ---- threshold pass in float domain (streaming stores) ----
    if (largest) {
        const float thr = __uint_as_float(ord2f(thr_ord));
        #pragma unroll
        for (int i = 0; i < V4; i++) {
            float4 o;
            o.x = (f[4*i+0] >= thr) ? f[4*i+0] : 0.0f;
            o.y = (f[4*i+1] >= thr) ? f[4*i+1] : 0.0f;
            o.z = (f[4*i+2] >= thr) ? f[4*i+2] : 0.0f;
            o.w = (f[4*i+3] >= thr) ? f[4*i+3] : 0.0f;
            __stcs(&xout[lane + 32 * i], o);
        }
    } else {
        const float thr = __uint_as_float(ord2f(thr_ord ^ flip));
        #pragma unroll
        for (int i = 0; i < V4; i++) {
            float4 o;
            o.x = (f[4*i+0] <= thr) ? f[4*i+0] : 0.0f;
            o.y = (f[4*i+1] <= thr) ? f[4*i+1] : 0.0f;
            o.z = (f[4*i+2] <= thr) ? f[4*i+2] : 0.0f;
            o.w = (f[4*i+3] <= thr) ? f[4*i+3] : 0.0f;
            __stcs(&xout[lane + 32 * i], o);
        }
    }
}

extern "C" void kernel_launch(void* const* d_in, const int* in_sizes, int n_in,
                              void* d_out, int out_size)
{
    const float* x    = (const float*)d_in[0];
    const int*   kptr = (const int*)d_in[1];
    const int*   lptr = (const int*)d_in[2];
    float* out = (float*)d_out;

    int nrows = in_sizes[0] / C_DIM;
    int blocks = (nrows + WARPS - 1) / WARPS;
    topk_mask_kernel<<<blocks, WARPS * 32>>>(x, kptr, lptr, out, nrows);
}

// round 16
// speedup vs baseline: 1.0623x; 1.0623x over previous
#include <cuda_runtime.h>
#include <cstdint>

// FINAL (R12, the measured optimum): Per-row exact top-k masking (keep k
// largest/smallest along last axis, zero rest). One warp per row of C=768
// floats. Level-1: SWAR byte-plane binary search over all 768 top-bytes. The m
// active candidates (typically 15-55) are compacted to <=2 per lane via a tiny
// smem strip; remaining 3 bytes resolved by ballot-count binary search
// (single-ballot fast path when m<=32) with early unique-survivor exit. m>64
// falls back to exact masked plane searches; m==1 extracts directly.
// 48-reg cap / 10 CTAs of 128 threads: measured sharp optimum — caps of 40/42
// regs spill hot state (L1 traffic), 64+ regs kill occupancy.

#define FULL_MASK 0xFFFFFFFFu

constexpr int C_DIM = 768;
constexpr int V4    = 6;     // float4 loads per lane (24 values/lane)
constexpr int WARPS = 4;     // rows per block (128-thread CTAs)

__device__ __forceinline__ unsigned f2ord(unsigned b) {
    return b ^ (unsigned)(((int)b >> 31) | 0x80000000);
}
__device__ __forceinline__ unsigned ord2f(unsigned u) {
    return u ^ (unsigned)(0x80000000u | ~((unsigned)((int)u >> 31)));
}

// Level-1 (mask-free) byte search: all 768 bytes active.
__device__ __forceinline__ int search_plane_l1(const unsigned* pl, const unsigned* plm,
                                               int& r, int& m)
{
    const unsigned REP1 = 0x01010101u;
    const unsigned H    = 0x80808080u;
    unsigned acc = 0;
    #pragma unroll
    for (int j = 0; j < V4; j++) acc = __dp4a(pl[j] & H, REP1, acc);
    const int n1 = (int)(__reduce_add_sync(FULL_MASK, acc) >> 7);

    int lo = 0, hi = 128, flo, fhi, base;
    if (n1 >= r) {   // threshold byte has bit7 set
        base = 128; flo = n1; fhi = 0;
        #pragma unroll 1
        for (int it = 0; it < 7; it++) {
            int mid = (lo + hi) >> 1;
            unsigned crep = (unsigned)(128 - mid) * REP1;
            unsigned a2 = 0;
            #pragma unroll
            for (int j = 0; j < V4; j++) {
                unsigned s = plm[j] + crep;           // bit7 <=> low7 >= mid
                a2 = __dp4a(s & pl[j] & H, REP1, a2);
            }
            int cnt = (int)(__reduce_add_sync(FULL_MASK, a2) >> 7);
            if (cnt >= r) { lo = mid; flo = cnt; } else { hi = mid; fhi = cnt; }
        }
    } else {         // threshold byte has bit7 clear
        base = 0; flo = m; fhi = n1;
        #pragma unroll 1
        for (int it = 0; it < 7; it++) {
            int mid = (lo + hi) >> 1;
            unsigned crep = (unsigned)(128 - mid) * REP1;
            unsigned a2 = 0;
            #pragma unroll
            for (int j = 0; j < V4; j++) {
                unsigned s = plm[j] + crep;
                a2 = __dp4a((s | pl[j]) & H, REP1, a2);
            }
            int cnt = (int)(__reduce_add_sync(FULL_MASK, a2) >> 7);
            if (cnt >= r) { lo = mid; flo = cnt; } else { hi = mid; fhi = cnt; }
        }
    }
    r -= fhi;
    m  = flo - fhi;
    return base + lo;
}

// Masked byte search (fallback levels). msk: 0x80 per active byte.
__device__ __forceinline__ int search_plane(const unsigned* pl, const unsigned* plm,
                                            const unsigned* msk, int& r, int& m)
{
    const unsigned REP1 = 0x01010101u;
    unsigned acc = 0;
    #pragma unroll
    for (int j = 0; j < V4; j++) acc = __dp4a(pl[j] & msk[j], REP1, acc);
    const int n1 = (int)(__reduce_add_sync(FULL_MASK, acc) >> 7);

    int lo = 0, hi = 128, flo, fhi, base;
    if (n1 >= r) {
        base = 128; flo = n1; fhi = 0;
        #pragma unroll 1
        for (int it = 0; it < 7; it++) {
            int mid = (lo + hi) >> 1;
            unsigned crep = (unsigned)(128 - mid) * REP1;
            unsigned a2 = 0;
            #pragma unroll
            for (int j = 0; j < V4; j++) {
                unsigned s = plm[j] + crep;
                a2 = __dp4a(s & pl[j] & msk[j], REP1, a2);
            }
            int cnt = (int)(__reduce_add_sync(FULL_MASK, a2) >> 7);
            if (cnt >= r) { lo = mid; flo = cnt; } else { hi = mid; fhi = cnt; }
        }
    } else {
        base = 0; flo = m; fhi = n1;
        #pragma unroll 1
        for (int it = 0; it < 7; it++) {
            int mid = (lo + hi) >> 1;
            unsigned crep = (unsigned)(128 - mid) * REP1;
            unsigned a2 = 0;
            #pragma unroll
            for (int j = 0; j < V4; j++) {
                unsigned s = plm[j] + crep;
                a2 = __dp4a((s | pl[j]) & msk[j], REP1, a2);
            }
            int cnt = (int)(__reduce_add_sync(FULL_MASK, a2) >> 7);
            if (cnt >= r) { lo = mid; flo = cnt; } else { hi = mid; fhi = cnt; }
        }
    }
    r -= fhi;
    m  = flo - fhi;
    return base + lo;
}

// First refine: msk is BORN here as the byte-equality mask.
__device__ __forceinline__ void refine_mask_init(unsigned* msk, const unsigned* pl,
                                                 const unsigned* plm, int d)
{
    const unsigned NH = 0x7F7F7F7Fu;
    const unsigned H  = 0x80808080u;
    const unsigned drep = (unsigned)d * 0x01010101u;
    const unsigned dr7  = drep & NH;
    #pragma unroll
    for (int j = 0; j < V4; j++) {
        unsigned z = pl[j] ^ drep;
        unsigned a = (plm[j] ^ dr7) + NH;
        msk[j] = ~a & ~z & H;                    // one LOP3
    }
}

// Subsequent refines: intersect with existing msk.
__device__ __forceinline__ void refine_mask(unsigned* msk, const unsigned* pl,
                                            const unsigned* plm, int d)
{
    const unsigned NH = 0x7F7F7F7Fu;
    const unsigned drep = (unsigned)d * 0x01010101u;
    const unsigned dr7  = drep & NH;
    #pragma unroll
    for (int j = 0; j < V4; j++) {
        unsigned z = pl[j] ^ drep;
        unsigned a = (plm[j] ^ dr7) + NH;
        msk[j] = ~a & ~z & msk[j];               // one LOP3 (msk is 0x80-only)
    }
}

// Exactly one active byte remains: return its full ordered value (warp-wide).
__device__ __forceinline__ unsigned extract_unique(const unsigned* msk,
                                                   const float* f, unsigned flip)
{
    unsigned best = 0;
    #pragma unroll
    for (int j = 0; j < V4; j++) {
        unsigned y = msk[j];
        if (y) {
            #pragma unroll
            for (int b = 0; b < 4; b++)
                if (y & (0x80u << (8*b)))
                    best = f2ord(__float_as_uint(f[4*j+b])) ^ flip;
        }
    }
    return __reduce_max_sync(FULL_MASK, best);
}

__global__ __launch_bounds__(WARPS * 32, 10)
void topk_mask_kernel(const float* __restrict__ x,
                      const int* __restrict__ kptr,
                      const int* __restrict__ lptr,
                      float* __restrict__ out,
                      int nrows)
{
    __shared__ unsigned s_cand[WARPS][64];   // 1 KB: compacted candidates

    const int warp = threadIdx.x >> 5;
    const int lane = threadIdx.x & 31;
    const int row  = blockIdx.x * WARPS + warp;
    if (row >= nrows) return;

    const int k       = *kptr;
    const int largest = *lptr;
    const unsigned flip = largest ? 0u : 0xFFFFFFFFu;

    const float4* __restrict__ xin =
        reinterpret_cast<const float4*>(x + (size_t)row * C_DIM);
    float4* __restrict__ xout =
        reinterpret_cast<float4*>(out + (size_t)row * C_DIM);

    const unsigned H  = 0x80808080u;
    const unsigned NH = 0x7F7F7F7Fu;
    const unsigned HX = H ^ flip;

    // ---- load x (streaming); pack ordered top-byte plane into p/pm ----
    float f[V4 * 4];
    unsigned p[V4], pm[V4], msk[V4];
    #pragma unroll
    for (int j = 0; j < V4; j++) {
        float4 v = __ldcs(&xin[lane + 32 * j]);
        f[4*j+0] = v.x; f[4*j+1] = v.y; f[4*j+2] = v.z; f[4*j+3] = v.w;
        unsigned p01 = __byte_perm(__float_as_uint(v.x), __float_as_uint(v.y), 0x0073);
        unsigned p23 = __byte_perm(__float_as_uint(v.z), __float_as_uint(v.w), 0x0073);
        unsigned pk  = __byte_perm(p01, p23, 0x5410);
        unsigned s   = pk & H;
        unsigned mm  = (s >> 7) * 0x7Fu;   // ordered-byte transform for negatives
        p[j]  = pk ^ mm ^ HX;
        pm[j] = p[j] & NH;
    }

    // ---- level 1: top byte (mask-free) ----
    int r = k, m = C_DIM;
    int d = search_plane_l1(p, pm, r, m);
    unsigned cur = (unsigned)d << 24;
    refine_mask_init(msk, p, pm, d);

    unsigned thr_ord;

    if (m == 1) {
        thr_ord = extract_unique(msk, f, flip);
    } else if (m <= 64) {
        // ---- compact the m candidates into smem (scan + predicated writes) ----
        int ci = 0;
        #pragma unroll
        for (int j = 0; j < V4; j++) ci += __popc(msk[j]);
        int sc = ci;
        #pragma unroll
        for (int sh = 1; sh < 32; sh <<= 1) {
            int t = __shfl_up_sync(FULL_MASK, sc, sh);
            if (lane >= sh) sc += t;
        }
        unsigned* cand = s_cand[warp];
        int pos = sc - ci;                       // exclusive prefix
        #pragma unroll
        for (int j = 0; j < V4; j++) {
            unsigned y = msk[j];
            if (y) {
                #pragma unroll
                for (int b = 0; b < 4; b++)
                    if (y & (0x80u << (8*b)))
                        cand[pos++] = f2ord(__float_as_uint(f[4*j+b])) ^ flip;
            }
        }
        __syncwarp();

        if (m <= 32) {
            // single candidate per lane: one ballot per probe
            bool a0 = lane < m;
            unsigned c0 = a0 ? cand[lane] : 0u;
            bool res2 = false;
            #pragma unroll 1
            for (int sh = 16; sh >= 0; sh -= 8) {
                int b0v = (int)((c0 >> sh) & 0xFFu);
                int lo = 0, hi = 256, fhi = 0;
                #pragma unroll 1
                for (int it = 0; it < 8; it++) {
                    int mid = (lo + hi) >> 1;
                    int cnt = __popc(__ballot_sync(FULL_MASK, a0 && (b0v >= mid)));
                    if (cnt >= r) { lo = mid; } else { hi = mid; fhi = cnt; }
                }
                r -= fhi;
                cur |= (unsigned)lo << sh;
                a0 = a0 && (b0v == lo);
                if (__popc(__ballot_sync(FULL_MASK, a0)) == 1) {
                    unsigned best = a0 ? c0 : 0u;
                    thr_ord = __reduce_max_sync(FULL_MASK, best);
                    res2 = true;
                    break;
                }
            }
            if (!res2) thr_ord = cur;
        } else {
            // <=2 candidates per lane
            bool a0 = true;                      // lane < m (m > 32)
            bool a1 = 32 + lane < m;
            unsigned c0 = cand[lane];
            unsigned c1 = a1 ? cand[32 + lane] : 0u;
            bool res2 = false;
            #pragma unroll 1
            for (int sh = 16; sh >= 0; sh -= 8) {
                int b0v = (int)((c0 >> sh) & 0xFFu);
                int b1v = (int)((c1 >> sh) & 0xFFu);
                int lo = 0, hi = 256, fhi = 0;
                #pragma unroll 1
                for (int it = 0; it < 8; it++) {
                    int mid = (lo + hi) >> 1;
                    unsigned bal0 = __ballot_sync(FULL_MASK, a0 && (b0v >= mid));
                    unsigned bal1 = __ballot_sync(FULL_MASK, a1 && (b1v >= mid));
                    int cnt = __popc(bal0) + __popc(bal1);
                    if (cnt >= r) { lo = mid; } else { hi = mid; fhi = cnt; }
                }
                r -= fhi;
                cur |= (unsigned)lo << sh;
                a0 = a0 && (b0v == lo);
                a1 = a1 && (b1v == lo);
                unsigned s0 = __ballot_sync(FULL_MASK, a0);
                unsigned s1 = __ballot_sync(FULL_MASK, a1);
                if (__popc(s0) + __popc(s1) == 1) {
                    unsigned best = a0 ? c0 : (a1 ? c1 : 0u);
                    thr_ord = __reduce_max_sync(FULL_MASK, best);
                    res2 = true;
                    break;
                }
            }
            if (!res2) thr_ord = cur;
        }
    } else {
        // ---- rare heavy bin (m > 64): exact masked plane searches over
        //      ordered-converted data, bytes 2,1,0. ----
        #pragma unroll
        for (int i = 0; i < V4 * 4; i++)
            f[i] = __uint_as_float(f2ord(__float_as_uint(f[i])) ^ flip);

        #pragma unroll
        for (int j = 0; j < V4; j++) {
            unsigned a01 = __byte_perm(__float_as_uint(f[4*j+0]),
                                       __float_as_uint(f[4*j+1]), 0x0062);
            unsigned a23 = __byte_perm(__float_as_uint(f[4*j+2]),
                                       __float_as_uint(f[4*j+3]), 0x0062);
            p[j]  = __byte_perm(a01, a23, 0x5410);   // byte2 plane (ordered)
            pm[j] = p[j] & NH;
        }
        int d2 = search_plane(p, pm, msk, r, m);
        cur |= (unsigned)d2 << 16;
        refine_mask(msk, p, pm, d2);

        #pragma unroll
        for (int j = 0; j < V4; j++) {
            unsigned a01 = __byte_perm(__float_as_uint(f[4*j+0]),
                                       __float_as_uint(f[4*j+1]), 0x0051);
            unsigned a23 = __byte_perm(__float_as_uint(f[4*j+2]),
                                       __float_as_uint(f[4*j+3]), 0x0051);
            p[j]  = __byte_perm(a01, a23, 0x5410);   // byte1 plane (ordered)
            pm[j] = p[j] & NH;
        }
        int d3 = search_plane(p, pm, msk, r, m);
        cur |= (unsigned)d3 << 8;
        refine_mask(msk, p, pm, d3);

        #pragma unroll
        for (int j = 0; j < V4; j++) {
            unsigned a01 = __byte_perm(__float_as_uint(f[4*j+0]),
                                       __float_as_uint(f[4*j+1]), 0x0040);
            unsigned a23 = __byte_perm(__float_as_uint(f[4*j+2]),
                                       __float_as_uint(f[4*j+3]), 0x0040);
            p[j]  = __byte_perm(a01, a23, 0x5410);   // byte0 plane (ordered)
            pm[j] = p[j] & NH;
        }
        int d4 = search_plane(p, pm, msk, r, m);
        cur |= (unsigned)d4;
        thr_ord = cur;                               // exact (duplicates too)

        // restore f to raw floats
        #pragma unroll
        for (int i = 0; i < V4 * 4; i++)
            f[i] = __uint_as_float(ord2f(__float_as_uint(f[i]) ^ flip));
    }

    // ---- threshold pass in float domain (streaming stores) ----
    if (largest) {
        const float thr = __uint_as_float(ord2f(thr_ord));
        #pragma unroll
        for (int i = 0; i < V4; i++) {
            float4 o;
            o.x = (f[4*i+0] >= thr) ? f[4*i+0] : 0.0f;
            o.y = (f[4*i+1] >= thr) ? f[4*i+1] : 0.0f;
            o.z = (f[4*i+2] >= thr) ? f[4*i+2] : 0.0f;
            o.w = (f[4*i+3] >= thr) ? f[4*i+3] : 0.0f;
            __stcs(&xout[lane + 32 * i], o);
        }
    } else {
        const float thr = __uint_as_float(ord2f(thr_ord ^ flip));
        #pragma unroll
        for (int i = 0; i < V4; i++) {
            float4 o;
            o.x = (f[4*i+0] <= thr) ? f[4*i+0] : 0.0f;
            o.y = (f[4*i+1] <= thr) ? f[4*i+1] : 0.0f;
            o.z = (f[4*i+2] <= thr) ? f[4*i+2] : 0.0f;
            o.w = (f[4*i+3] <= thr) ? f[4*i+3] : 0.0f;
            __stcs(&xout[lane + 32 * i], o);
        }
    }
}

extern "C" void kernel_launch(void* const* d_in, const int* in_sizes, int n_in,
                              void* d_out, int out_size)
{
    const float* x    = (const float*)d_in[0];
    const int*   kptr = (const int*)d_in[1];
    const int*   lptr = (const int*)d_in[2];
    float* out = (float*)d_out;

    int nrows = in_sizes[0] / C_DIM;
    int blocks = (nrows + WARPS - 1) / WARPS;
    topk_mask_kernel<<<blocks, WARPS * 32>>>(x, kptr, lptr, out, nrows);
}